// round 1
// baseline (speedup 1.0000x reference)
#include <cuda_runtime.h>
#include <cstdint>

#define NB 4
#define NS 4096
#define ND 1024
#define NV 32000
#define ND3 3072

#define QK_DSPLIT 32
#define QK_DCH (ND / QK_DSPLIT)      // 32
#define HB_CHUNK 64
#define HB_ROWS (NS / HB_CHUNK)      // 64
#define V_DSPLIT 32
#define V_DCH (ND / V_DSPLIT)        // 32
#define O_DSPLIT 8
#define O_DCH (ND / O_DSPLIT)        // 128

// ---------------- scratch (device globals; no allocation allowed) ----------
__device__ int   g_odd_nonzero;                       // 0 => x is int64
__device__ __align__(16) float g_hlast[NB][ND];
__device__ __align__(16) float g_q_part[QK_DSPLIT][NB][ND];
__device__ __align__(16) float g_qlast[NB][ND];
__device__ __align__(16) float g_qk[NB][ND];          // pre-scaled by 1/32
__device__ float g_qbk[NB];                           // pre-scaled by 1/32
__device__ __align__(16) float g_logits[NB][NS];      // reused as attn
__device__ __align__(16) float g_hbar_part[HB_CHUNK][NB][ND];
__device__ __align__(16) float g_v_part[V_DSPLIT][NB][ND];
__device__ __align__(16) float g_hfinal[NB][ND];
__device__ __align__(16) float g_out_part[O_DSPLIT][NB][NV];

__device__ __forceinline__ int get_idx(const void* x, int i, bool is64) {
    if (is64) return (int)((const long long*)x)[i];
    return ((const int*)x)[i];
}

// ---------------- K0: detect int64 vs int32 token buffer -------------------
// Only touches the first 16384 int32 words (= min possible buffer size).
// If x is int64, odd words are the (zero) high halves of the first 8192 tokens.
__global__ void k0_detect(const int* __restrict__ x32) {
    int i = blockIdx.x * blockDim.x + threadIdx.x;   // 0..8191
    int v = (i < 8192) ? x32[2 * i + 1] : 0;
    if (__syncthreads_or(v)) {
        if (threadIdx.x == 0) atomicOr(&g_odd_nonzero, 1);
    }
}

// ---------------- K1a: q_last partials = h_last @ Wq (d-split) -------------
__global__ void k1a_qpart(const void* __restrict__ x,
                          const float* __restrict__ embed,
                          const float* __restrict__ qkv_w) {
    __shared__ float sh[NB][QK_DCH];
    const bool is64 = (g_odd_nonzero == 0);
    const int dch = blockIdx.y;
    const int tid = threadIdx.x;
    if (tid < NB * QK_DCH) {
        int b = tid >> 5, d = tid & (QK_DCH - 1);
        int row = get_idx(x, b * NS + NS - 1, is64);
        float v = embed[(size_t)row * ND + dch * QK_DCH + d];
        sh[b][d] = v;
        if (blockIdx.x == 0) g_hlast[b][dch * QK_DCH + d] = v;
    }
    __syncthreads();
    int j = blockIdx.x * 256 + tid;
    const float* wp = qkv_w + (size_t)(dch * QK_DCH) * ND3 + j;
    float a0 = 0.f, a1 = 0.f, a2 = 0.f, a3 = 0.f;
#pragma unroll 8
    for (int d = 0; d < QK_DCH; d++) {
        float w = wp[(size_t)d * ND3];
        a0 = fmaf(sh[0][d], w, a0);
        a1 = fmaf(sh[1][d], w, a1);
        a2 = fmaf(sh[2][d], w, a2);
        a3 = fmaf(sh[3][d], w, a3);
    }
    g_q_part[dch][0][j] = a0;
    g_q_part[dch][1][j] = a1;
    g_q_part[dch][2][j] = a2;
    g_q_part[dch][3][j] = a3;
}

// ---------------- K1ar: reduce partials + bias -> q_last -------------------
__global__ void k1ar_qreduce(const float* __restrict__ qkv_b) {
    int idx = blockIdx.x * 256 + threadIdx.x;     // 0..4095
    int b = idx >> 10, j = idx & (ND - 1);
    float s = qkv_b[j];
#pragma unroll
    for (int c = 0; c < QK_DSPLIT; c++) s += g_q_part[c][b][j];
    g_qlast[b][j] = s;
}

// ---------------- K1b: qk = Wk @ q_last (row-dot), qbk = q_last . bk -------
__global__ void k1b_qk(const float* __restrict__ qkv_w,
                       const float* __restrict__ qkv_b) {
    const int warp = threadIdx.x >> 5, lane = threadIdx.x & 31;
    const float kInv = 0.03125f;                  // 1/sqrt(1024)
    if (blockIdx.x < 128) {
        int d = blockIdx.x * 8 + warp;
        const float4* wrow = (const float4*)(qkv_w + (size_t)d * ND3 + ND);
        float a0 = 0.f, a1 = 0.f, a2 = 0.f, a3 = 0.f;
#pragma unroll
        for (int it = 0; it < 8; it++) {
            int p = lane + 32 * it;
            float4 w  = wrow[p];
            float4 q0 = ((const float4*)g_qlast[0])[p];
            float4 q1 = ((const float4*)g_qlast[1])[p];
            float4 q2 = ((const float4*)g_qlast[2])[p];
            float4 q3 = ((const float4*)g_qlast[3])[p];
            a0 = fmaf(w.x, q0.x, fmaf(w.y, q0.y, fmaf(w.z, q0.z, fmaf(w.w, q0.w, a0))));
            a1 = fmaf(w.x, q1.x, fmaf(w.y, q1.y, fmaf(w.z, q1.z, fmaf(w.w, q1.w, a1))));
            a2 = fmaf(w.x, q2.x, fmaf(w.y, q2.y, fmaf(w.z, q2.z, fmaf(w.w, q2.w, a2))));
            a3 = fmaf(w.x, q3.x, fmaf(w.y, q3.y, fmaf(w.z, q3.z, fmaf(w.w, q3.w, a3))));
        }
#pragma unroll
        for (int o = 16; o > 0; o >>= 1) {
            a0 += __shfl_xor_sync(0xffffffffu, a0, o);
            a1 += __shfl_xor_sync(0xffffffffu, a1, o);
            a2 += __shfl_xor_sync(0xffffffffu, a2, o);
            a3 += __shfl_xor_sync(0xffffffffu, a3, o);
        }
        if (lane == 0) {
            g_qk[0][d] = a0 * kInv;
            g_qk[1][d] = a1 * kInv;
            g_qk[2][d] = a2 * kInv;
            g_qk[3][d] = a3 * kInv;
        }
    } else {
        if (warp < NB) {
            const float4* bk = (const float4*)(qkv_b + ND);
            const float4* q  = (const float4*)g_qlast[warp];
            float a = 0.f;
#pragma unroll
            for (int it = 0; it < 8; it++) {
                int p = lane + 32 * it;
                float4 w = bk[p];
                float4 qq = q[p];
                a = fmaf(w.x, qq.x, fmaf(w.y, qq.y, fmaf(w.z, qq.z, fmaf(w.w, qq.w, a))));
            }
#pragma unroll
            for (int o = 16; o > 0; o >>= 1) a += __shfl_xor_sync(0xffffffffu, a, o);
            if (lane == 0) g_qbk[warp] = a * kInv;
        }
    }
}

// ---------------- K2: logits[b][s] = embed[x[b,s]] . qk[b] + qbk[b] --------
__global__ void k2_logits(const void* __restrict__ x,
                          const float* __restrict__ embed) {
    __shared__ float4 sqk[256];
    const int b = blockIdx.y;
    const bool is64 = (g_odd_nonzero == 0);
    sqk[threadIdx.x] = ((const float4*)g_qk[b])[threadIdx.x];
    __syncthreads();
    const int warp = threadIdx.x >> 5, lane = threadIdx.x & 31;
    const int s = blockIdx.x * 8 + warp;
    const int row = get_idx(x, b * NS + s, is64);
    const float4* e = (const float4*)(embed + (size_t)row * ND);
    float a = 0.f;
#pragma unroll
    for (int it = 0; it < 8; it++) {
        int p = lane + 32 * it;
        float4 ev = e[p];
        float4 q  = sqk[p];
        a = fmaf(ev.x, q.x, fmaf(ev.y, q.y, fmaf(ev.z, q.z, fmaf(ev.w, q.w, a))));
    }
#pragma unroll
    for (int o = 16; o > 0; o >>= 1) a += __shfl_xor_sync(0xffffffffu, a, o);
    if (lane == 0) g_logits[b][s] = a + g_qbk[b];
}

// ---------------- K3: softmax over 4096 keys, in place ---------------------
__global__ void k3_softmax() {
    __shared__ float red[32];
    __shared__ float bcast;
    const int b = blockIdx.x, t = threadIdx.x;
    const int lane = t & 31, warp = t >> 5;
    float l0 = g_logits[b][t];
    float l1 = g_logits[b][t + 1024];
    float l2 = g_logits[b][t + 2048];
    float l3 = g_logits[b][t + 3072];
    float m = fmaxf(fmaxf(l0, l1), fmaxf(l2, l3));
#pragma unroll
    for (int o = 16; o > 0; o >>= 1) m = fmaxf(m, __shfl_xor_sync(0xffffffffu, m, o));
    if (lane == 0) red[warp] = m;
    __syncthreads();
    if (t < 32) {
        float mm = red[t];
#pragma unroll
        for (int o = 16; o > 0; o >>= 1) mm = fmaxf(mm, __shfl_xor_sync(0xffffffffu, mm, o));
        if (t == 0) bcast = mm;
    }
    __syncthreads();
    const float M = bcast;
    float e0 = expf(l0 - M), e1 = expf(l1 - M), e2 = expf(l2 - M), e3 = expf(l3 - M);
    float s = (e0 + e1) + (e2 + e3);
#pragma unroll
    for (int o = 16; o > 0; o >>= 1) s += __shfl_xor_sync(0xffffffffu, s, o);
    __syncthreads();   // protect red[] reuse
    if (lane == 0) red[warp] = s;
    __syncthreads();
    if (t < 32) {
        float ss = red[t];
#pragma unroll
        for (int o = 16; o > 0; o >>= 1) ss += __shfl_xor_sync(0xffffffffu, ss, o);
        if (t == 0) bcast = ss;
    }
    __syncthreads();
    const float inv = 1.0f / bcast;
    g_logits[b][t]        = e0 * inv;
    g_logits[b][t + 1024] = e1 * inv;
    g_logits[b][t + 2048] = e2 * inv;
    g_logits[b][t + 3072] = e3 * inv;
}

// ---------------- K4: hbar partials = sum_s attn[b,s] * embed[x[b,s]] ------
__global__ void k4_hbar(const void* __restrict__ x,
                        const float* __restrict__ embed) {
    const int c = blockIdx.x, b = blockIdx.y;
    const bool is64 = (g_odd_nonzero == 0);
    const int t = threadIdx.x;
    float4 acc = make_float4(0.f, 0.f, 0.f, 0.f);
    const int s0 = c * HB_ROWS;
#pragma unroll 4
    for (int r = 0; r < HB_ROWS; r++) {
        int s = s0 + r;
        float w = g_logits[b][s];
        int row = get_idx(x, b * NS + s, is64);
        float4 e = ((const float4*)(embed + (size_t)row * ND))[t];
        acc.x = fmaf(w, e.x, acc.x);
        acc.y = fmaf(w, e.y, acc.y);
        acc.z = fmaf(w, e.z, acc.z);
        acc.w = fmaf(w, e.w, acc.w);
    }
    ((float4*)g_hbar_part[c][b])[t] = acc;
}

// ---------------- K5a: v partials = hbar @ Wv (d-split) --------------------
__global__ void k5a_vpart(const float* __restrict__ qkv_w) {
    __shared__ float sh[NB][V_DCH];
    const int dch = blockIdx.y;
    const int tid = threadIdx.x;
    if (tid < NB * V_DCH) {
        int b = tid >> 5, d = tid & (V_DCH - 1);
        float s = 0.f;
#pragma unroll 8
        for (int c = 0; c < HB_CHUNK; c++) s += g_hbar_part[c][b][dch * V_DCH + d];
        sh[b][d] = s;
    }
    __syncthreads();
    int j = blockIdx.x * 256 + tid;
    const float* wp = qkv_w + (size_t)(dch * V_DCH) * ND3 + 2048 + j;
    float a0 = 0.f, a1 = 0.f, a2 = 0.f, a3 = 0.f;
#pragma unroll 8
    for (int d = 0; d < V_DCH; d++) {
        float w = wp[(size_t)d * ND3];
        a0 = fmaf(sh[0][d], w, a0);
        a1 = fmaf(sh[1][d], w, a1);
        a2 = fmaf(sh[2][d], w, a2);
        a3 = fmaf(sh[3][d], w, a3);
    }
    g_v_part[dch][0][j] = a0;
    g_v_part[dch][1][j] = a1;
    g_v_part[dch][2][j] = a2;
    g_v_part[dch][3][j] = a3;
}

// ---------------- K5r: hfinal = attn_out + bv + h_last ---------------------
__global__ void k5r_vreduce(const float* __restrict__ qkv_b) {
    int idx = blockIdx.x * 256 + threadIdx.x;   // 0..4095
    int b = idx >> 10, j = idx & (ND - 1);
    float s = qkv_b[2048 + j];
#pragma unroll
    for (int c = 0; c < V_DSPLIT; c++) s += g_v_part[c][b][j];
    g_hfinal[b][j] = s + g_hlast[b][j];
}

// ---------------- K6: out partials = hfinal @ out_w (d-split) --------------
__global__ void k6_out(const float* __restrict__ out_w) {
    __shared__ float sh[NB][O_DCH];
    const int dc = blockIdx.y;
    for (int t = threadIdx.x; t < NB * O_DCH; t += 256) {
        int b = t >> 7, d = t & (O_DCH - 1);
        sh[b][d] = g_hfinal[b][dc * O_DCH + d];
    }
    __syncthreads();
    const int v = blockIdx.x * 256 + threadIdx.x;
    const float* wp = out_w + (size_t)(dc * O_DCH) * NV + v;
    float a0 = 0.f, a1 = 0.f, a2 = 0.f, a3 = 0.f;
#pragma unroll 8
    for (int d = 0; d < O_DCH; d++) {
        float w = wp[(size_t)d * NV];
        a0 = fmaf(sh[0][d], w, a0);
        a1 = fmaf(sh[1][d], w, a1);
        a2 = fmaf(sh[2][d], w, a2);
        a3 = fmaf(sh[3][d], w, a3);
    }
    g_out_part[dc][0][v] = a0;
    g_out_part[dc][1][v] = a1;
    g_out_part[dc][2][v] = a2;
    g_out_part[dc][3][v] = a3;
}

// ---------------- K7: reduce partials + out_b -> d_out ---------------------
__global__ void k7_reduce(const float* __restrict__ out_b,
                          float* __restrict__ out) {
    const int v = blockIdx.x * 256 + threadIdx.x;
    const float ob = out_b[v];
#pragma unroll
    for (int b = 0; b < NB; b++) {
        float s = ob;
#pragma unroll
        for (int dc = 0; dc < O_DSPLIT; dc++) s += g_out_part[dc][b][v];
        out[b * NV + v] = s;
    }
}

extern "C" void kernel_launch(void* const* d_in, const int* in_sizes, int n_in,
                              void* d_out, int out_size) {
    const void*  x      = d_in[0];
    const float* embed  = (const float*)d_in[1];
    const float* qkv_w  = (const float*)d_in[2];
    const float* qkv_b  = (const float*)d_in[3];
    const float* out_w  = (const float*)d_in[4];
    const float* out_b  = (const float*)d_in[5];
    float* out = (float*)d_out;

    k0_detect<<<32, 256>>>((const int*)x);
    k1a_qpart<<<dim3(4, QK_DSPLIT), 256>>>(x, embed, qkv_w);
    k1ar_qreduce<<<16, 256>>>(qkv_b);
    k1b_qk<<<129, 256>>>(qkv_w, qkv_b);
    k2_logits<<<dim3(NS / 8, NB), 256>>>(x, embed);
    k3_softmax<<<NB, 1024>>>();
    k4_hbar<<<dim3(HB_CHUNK, NB), 256>>>(x, embed);
    k5a_vpart<<<dim3(4, V_DSPLIT), 256>>>(qkv_w);
    k5r_vreduce<<<16, 256>>>(qkv_b);
    k6_out<<<dim3(NV / 256, O_DSPLIT), 256>>>(out_w);
    k7_reduce<<<NV / 256, 256>>>(out_b, out);
}

// round 2
// speedup vs baseline: 1.1051x; 1.1051x over previous
#include <cuda_runtime.h>
#include <cstdint>

#define NB 4
#define NS 4096
#define ND 1024
#define NV 32000
#define ND3 3072

#define QK_DSPLIT 64
#define QK_DCH (ND / QK_DSPLIT)      // 16
#define HB_CHUNK 128
#define HB_ROWS (NS / HB_CHUNK)      // 32
#define V_DSPLIT 64
#define V_DCH (ND / V_DSPLIT)        // 16
#define O_DSPLIT 8
#define O_DCH (ND / O_DSPLIT)        // 128

// ---------------- scratch (device globals; no allocation allowed) ----------
__device__ int   g_odd_nonzero;                       // 0 => x is int64
__device__ __align__(16) float g_hlast[NB][ND];
__device__ __align__(16) float g_q_part[QK_DSPLIT][NB][ND];
__device__ __align__(16) float g_qlast[NB][ND];
__device__ __align__(16) float g_qk[NB][ND];          // pre-scaled by 1/32
__device__ float g_qbk[NB];                           // pre-scaled by 1/32
__device__ __align__(16) float g_logits[NB][NS];      // reused as attn
__device__ __align__(16) float g_hbar_part[HB_CHUNK][NB][ND];
__device__ __align__(16) float g_v_part[V_DSPLIT][NB][ND];
__device__ __align__(16) float g_hfinal[NB][ND];
__device__ __align__(16) float g_out_part[O_DSPLIT][NB][NV];

__device__ __forceinline__ int get_idx(const void* x, int i, bool is64) {
    if (is64) return (int)((const long long*)x)[i];
    return ((const int*)x)[i];
}

// ---------------- K0: detect int64 vs int32 token buffer -------------------
__global__ void k0_detect(const int* __restrict__ x32) {
    int i = blockIdx.x * blockDim.x + threadIdx.x;   // 0..8191
    int v = (i < 8192) ? x32[2 * i + 1] : 0;
    if (__syncthreads_or(v)) {
        if (threadIdx.x == 0) atomicOr(&g_odd_nonzero, 1);
    }
}

// ---------------- K1a: q_last partials = h_last @ Wq (d-split) -------------
__global__ void k1a_qpart(const void* __restrict__ x,
                          const float* __restrict__ embed,
                          const float* __restrict__ qkv_w) {
    __shared__ float sh[NB][QK_DCH];
    const bool is64 = (g_odd_nonzero == 0);
    const int dch = blockIdx.y;
    const int tid = threadIdx.x;
    if (tid < NB * QK_DCH) {
        int b = tid / QK_DCH, d = tid % QK_DCH;
        int row = get_idx(x, b * NS + NS - 1, is64);
        float v = embed[(size_t)row * ND + dch * QK_DCH + d];
        sh[b][d] = v;
        if (blockIdx.x == 0) g_hlast[b][dch * QK_DCH + d] = v;
    }
    __syncthreads();
    int j = blockIdx.x * 256 + tid;
    const float* wp = qkv_w + (size_t)(dch * QK_DCH) * ND3 + j;
    float a0 = 0.f, a1 = 0.f, a2 = 0.f, a3 = 0.f;
#pragma unroll
    for (int d = 0; d < QK_DCH; d++) {
        float w = wp[(size_t)d * ND3];
        a0 = fmaf(sh[0][d], w, a0);
        a1 = fmaf(sh[1][d], w, a1);
        a2 = fmaf(sh[2][d], w, a2);
        a3 = fmaf(sh[3][d], w, a3);
    }
    g_q_part[dch][0][j] = a0;
    g_q_part[dch][1][j] = a1;
    g_q_part[dch][2][j] = a2;
    g_q_part[dch][3][j] = a3;
}

// ---------------- K1ar: reduce partials + bias -> q_last -------------------
__global__ void k1ar_qreduce(const float* __restrict__ qkv_b) {
    int idx = blockIdx.x * 128 + threadIdx.x;     // 0..4095, 32 blocks
    int b = idx >> 10, j = idx & (ND - 1);
    float s = qkv_b[j];
#pragma unroll
    for (int c = 0; c < QK_DSPLIT; c++) s += g_q_part[c][b][j];
    g_qlast[b][j] = s;
}

// ---------------- K1b: qk[j] = Wk-row(j) . q_last, block per row -----------
__global__ void k1b_qk(const float* __restrict__ qkv_w,
                       const float* __restrict__ qkv_b) {
    __shared__ float red[8][NB];
    const int warp = threadIdx.x >> 5, lane = threadIdx.x & 31;
    const float kInv = 0.03125f;                  // 1/sqrt(1024)
    if (blockIdx.x < 1024) {
        const int j = blockIdx.x;
        const int p = warp * 32 + lane;           // 0..255 float4 index
        const float4 w  = ((const float4*)(qkv_w + (size_t)j * ND3 + ND))[p];
        const float4 q0 = ((const float4*)g_qlast[0])[p];
        const float4 q1 = ((const float4*)g_qlast[1])[p];
        const float4 q2 = ((const float4*)g_qlast[2])[p];
        const float4 q3 = ((const float4*)g_qlast[3])[p];
        float a0 = fmaf(w.x, q0.x, fmaf(w.y, q0.y, fmaf(w.z, q0.z, w.w * q0.w)));
        float a1 = fmaf(w.x, q1.x, fmaf(w.y, q1.y, fmaf(w.z, q1.z, w.w * q1.w)));
        float a2 = fmaf(w.x, q2.x, fmaf(w.y, q2.y, fmaf(w.z, q2.z, w.w * q2.w)));
        float a3 = fmaf(w.x, q3.x, fmaf(w.y, q3.y, fmaf(w.z, q3.z, w.w * q3.w)));
#pragma unroll
        for (int o = 16; o > 0; o >>= 1) {
            a0 += __shfl_xor_sync(0xffffffffu, a0, o);
            a1 += __shfl_xor_sync(0xffffffffu, a1, o);
            a2 += __shfl_xor_sync(0xffffffffu, a2, o);
            a3 += __shfl_xor_sync(0xffffffffu, a3, o);
        }
        if (lane == 0) {
            red[warp][0] = a0; red[warp][1] = a1;
            red[warp][2] = a2; red[warp][3] = a3;
        }
        __syncthreads();
        if (threadIdx.x < NB) {
            int b = threadIdx.x;
            float s = red[0][b];
#pragma unroll
            for (int ww = 1; ww < 8; ww++) s += red[ww][b];
            g_qk[b][j] = s * kInv;
        }
    } else {
        if (warp < NB) {
            const float4* bk = (const float4*)(qkv_b + ND);
            const float4* q  = (const float4*)g_qlast[warp];
            float a = 0.f;
#pragma unroll
            for (int it = 0; it < 8; it++) {
                int p = lane + 32 * it;
                float4 w = bk[p];
                float4 qq = q[p];
                a = fmaf(w.x, qq.x, fmaf(w.y, qq.y, fmaf(w.z, qq.z, fmaf(w.w, qq.w, a))));
            }
#pragma unroll
            for (int o = 16; o > 0; o >>= 1) a += __shfl_xor_sync(0xffffffffu, a, o);
            if (lane == 0) g_qbk[warp] = a * kInv;
        }
    }
}

// ---------------- K2: logits[b][s] = embed[x[b,s]] . qk[b] + qbk[b] --------
__global__ void k2_logits(const void* __restrict__ x,
                          const float* __restrict__ embed) {
    __shared__ float4 sqk[256];
    const int b = blockIdx.y;
    const bool is64 = (g_odd_nonzero == 0);
    sqk[threadIdx.x] = ((const float4*)g_qk[b])[threadIdx.x];
    __syncthreads();
    const int warp = threadIdx.x >> 5, lane = threadIdx.x & 31;
    const int s = blockIdx.x * 8 + warp;
    const int row = get_idx(x, b * NS + s, is64);
    const float4* e = (const float4*)(embed + (size_t)row * ND);
    float a = 0.f;
#pragma unroll
    for (int it = 0; it < 8; it++) {
        int p = lane + 32 * it;
        float4 ev = e[p];
        float4 q  = sqk[p];
        a = fmaf(ev.x, q.x, fmaf(ev.y, q.y, fmaf(ev.z, q.z, fmaf(ev.w, q.w, a))));
    }
#pragma unroll
    for (int o = 16; o > 0; o >>= 1) a += __shfl_xor_sync(0xffffffffu, a, o);
    if (lane == 0) g_logits[b][s] = a + g_qbk[b];
}

// ---------------- K3: softmax over 4096 keys, in place ---------------------
__global__ void k3_softmax() {
    __shared__ float red[32];
    __shared__ float bcast;
    const int b = blockIdx.x, t = threadIdx.x;
    const int lane = t & 31, warp = t >> 5;
    float l0 = g_logits[b][t];
    float l1 = g_logits[b][t + 1024];
    float l2 = g_logits[b][t + 2048];
    float l3 = g_logits[b][t + 3072];
    float m = fmaxf(fmaxf(l0, l1), fmaxf(l2, l3));
#pragma unroll
    for (int o = 16; o > 0; o >>= 1) m = fmaxf(m, __shfl_xor_sync(0xffffffffu, m, o));
    if (lane == 0) red[warp] = m;
    __syncthreads();
    if (t < 32) {
        float mm = red[t];
#pragma unroll
        for (int o = 16; o > 0; o >>= 1) mm = fmaxf(mm, __shfl_xor_sync(0xffffffffu, mm, o));
        if (t == 0) bcast = mm;
    }
    __syncthreads();
    const float M = bcast;
    float e0 = expf(l0 - M), e1 = expf(l1 - M), e2 = expf(l2 - M), e3 = expf(l3 - M);
    float s = (e0 + e1) + (e2 + e3);
#pragma unroll
    for (int o = 16; o > 0; o >>= 1) s += __shfl_xor_sync(0xffffffffu, s, o);
    __syncthreads();
    if (lane == 0) red[warp] = s;
    __syncthreads();
    if (t < 32) {
        float ss = red[t];
#pragma unroll
        for (int o = 16; o > 0; o >>= 1) ss += __shfl_xor_sync(0xffffffffu, ss, o);
        if (t == 0) bcast = ss;
    }
    __syncthreads();
    const float inv = 1.0f / bcast;
    g_logits[b][t]        = e0 * inv;
    g_logits[b][t + 1024] = e1 * inv;
    g_logits[b][t + 2048] = e2 * inv;
    g_logits[b][t + 3072] = e3 * inv;
}

// ---------------- K4: hbar partials = sum_s attn[b,s] * embed[x[b,s]] ------
__global__ void k4_hbar(const void* __restrict__ x,
                        const float* __restrict__ embed) {
    const int c = blockIdx.x, b = blockIdx.y;
    const bool is64 = (g_odd_nonzero == 0);
    const int t = threadIdx.x;
    float4 acc = make_float4(0.f, 0.f, 0.f, 0.f);
    const int s0 = c * HB_ROWS;
#pragma unroll 4
    for (int r = 0; r < HB_ROWS; r++) {
        int s = s0 + r;
        float w = g_logits[b][s];
        int row = get_idx(x, b * NS + s, is64);
        float4 e = ((const float4*)(embed + (size_t)row * ND))[t];
        acc.x = fmaf(w, e.x, acc.x);
        acc.y = fmaf(w, e.y, acc.y);
        acc.z = fmaf(w, e.z, acc.z);
        acc.w = fmaf(w, e.w, acc.w);
    }
    ((float4*)g_hbar_part[c][b])[t] = acc;
}

// ---------------- K5a: v partials = hbar @ Wv (d-split) --------------------
__global__ void k5a_vpart(const float* __restrict__ qkv_w) {
    __shared__ float sh[NB][V_DCH];
    const int dch = blockIdx.y;
    const int tid = threadIdx.x;
    if (tid < NB * V_DCH) {
        int b = tid / V_DCH, d = tid % V_DCH;
        float s = 0.f;
#pragma unroll 8
        for (int c = 0; c < HB_CHUNK; c++) s += g_hbar_part[c][b][dch * V_DCH + d];
        sh[b][d] = s;
    }
    __syncthreads();
    int j = blockIdx.x * 256 + tid;
    const float* wp = qkv_w + (size_t)(dch * V_DCH) * ND3 + 2048 + j;
    float a0 = 0.f, a1 = 0.f, a2 = 0.f, a3 = 0.f;
#pragma unroll
    for (int d = 0; d < V_DCH; d++) {
        float w = wp[(size_t)d * ND3];
        a0 = fmaf(sh[0][d], w, a0);
        a1 = fmaf(sh[1][d], w, a1);
        a2 = fmaf(sh[2][d], w, a2);
        a3 = fmaf(sh[3][d], w, a3);
    }
    g_v_part[dch][0][j] = a0;
    g_v_part[dch][1][j] = a1;
    g_v_part[dch][2][j] = a2;
    g_v_part[dch][3][j] = a3;
}

// ---------------- K5r: hfinal = attn_out + bv + h_last ---------------------
__global__ void k5r_vreduce(const float* __restrict__ qkv_b) {
    int idx = blockIdx.x * 128 + threadIdx.x;   // 32 blocks
    int b = idx >> 10, j = idx & (ND - 1);
    float s = qkv_b[2048 + j];
#pragma unroll
    for (int c = 0; c < V_DSPLIT; c++) s += g_v_part[c][b][j];
    g_hfinal[b][j] = s + g_hlast[b][j];
}

// ---------------- K6: out partials = hfinal @ out_w (d-split) --------------
__global__ void k6_out(const float* __restrict__ out_w) {
    __shared__ float sh[NB][O_DCH];
    const int dc = blockIdx.y;
    for (int t = threadIdx.x; t < NB * O_DCH; t += 256) {
        int b = t >> 7, d = t & (O_DCH - 1);
        sh[b][d] = g_hfinal[b][dc * O_DCH + d];
    }
    __syncthreads();
    const int v = blockIdx.x * 256 + threadIdx.x;
    const float* wp = out_w + (size_t)(dc * O_DCH) * NV + v;
    float a0 = 0.f, a1 = 0.f, a2 = 0.f, a3 = 0.f;
#pragma unroll 8
    for (int d = 0; d < O_DCH; d++) {
        float w = wp[(size_t)d * NV];
        a0 = fmaf(sh[0][d], w, a0);
        a1 = fmaf(sh[1][d], w, a1);
        a2 = fmaf(sh[2][d], w, a2);
        a3 = fmaf(sh[3][d], w, a3);
    }
    g_out_part[dc][0][v] = a0;
    g_out_part[dc][1][v] = a1;
    g_out_part[dc][2][v] = a2;
    g_out_part[dc][3][v] = a3;
}

// ---------------- K7: reduce partials + out_b -> d_out ---------------------
__global__ void k7_reduce(const float* __restrict__ out_b,
                          float* __restrict__ out) {
    const int v = blockIdx.x * 256 + threadIdx.x;
    const float ob = out_b[v];
#pragma unroll
    for (int b = 0; b < NB; b++) {
        float s = ob;
#pragma unroll
        for (int dc = 0; dc < O_DSPLIT; dc++) s += g_out_part[dc][b][v];
        out[b * NV + v] = s;
    }
}

extern "C" void kernel_launch(void* const* d_in, const int* in_sizes, int n_in,
                              void* d_out, int out_size) {
    const void*  x      = d_in[0];
    const float* embed  = (const float*)d_in[1];
    const float* qkv_w  = (const float*)d_in[2];
    const float* qkv_b  = (const float*)d_in[3];
    const float* out_w  = (const float*)d_in[4];
    const float* out_b  = (const float*)d_in[5];
    float* out = (float*)d_out;

    k0_detect<<<32, 256>>>((const int*)x);
    k1a_qpart<<<dim3(4, QK_DSPLIT), 256>>>(x, embed, qkv_w);
    k1ar_qreduce<<<32, 128>>>(qkv_b);
    k1b_qk<<<1025, 256>>>(qkv_w, qkv_b);
    k2_logits<<<dim3(NS / 8, NB), 256>>>(x, embed);
    k3_softmax<<<NB, 1024>>>();
    k4_hbar<<<dim3(HB_CHUNK, NB), 256>>>(x, embed);
    k5a_vpart<<<dim3(4, V_DSPLIT), 256>>>(qkv_w);
    k5r_vreduce<<<32, 128>>>(qkv_b);
    k6_out<<<dim3(NV / 256, O_DSPLIT), 256>>>(out_w);
    k7_reduce<<<NV / 256, 256>>>(out_b, out);
}